// round 1
// baseline (speedup 1.0000x reference)
#include <cuda_runtime.h>
#include <math.h>

// ---------------- problem constants ----------------
#define QLEN    1024
#define BATCH   4
#define DMODEL  1024
#define NHEAD   16
#define HDIM    64
#define MEMLEN  512
#define KLENC   1536
#define MLPD    4096
#define ATT_SCALE 0.125f       // 1/sqrt(64)
#define NROWS   4096           // QLEN*BATCH
#define KROWS   6144           // KLENC*BATCH

// ---------------- scratch (device globals; allocation-free) ----------------
__device__ __align__(16) float g_cat[(size_t)KROWS * DMODEL];          // 25 MB
__device__ __align__(16) float g_qkv[(size_t)KROWS * 3 * DMODEL];      // 75 MB
__device__ __align__(16) float g_rh [(size_t)KLENC * DMODEL];          // 6 MB
__device__ __align__(16) float g_S  [(size_t)BATCH * NHEAD * QLEN * KLENC]; // 400 MB (scores, then attn in-place)
__device__ __align__(16) float g_ctx[(size_t)NROWS * DMODEL];          // 16 MB
__device__ __align__(16) float g_y  [(size_t)NROWS * DMODEL];
__device__ __align__(16) float g_x  [(size_t)NROWS * DMODEL];
__device__ __align__(16) float g_h  [(size_t)NROWS * MLPD];            // 64 MB
__device__ __align__(16) float g_y2 [(size_t)NROWS * DMODEL];

// ---------------- generic fp32 SGEMM: C = A@B (+bias)(+relu) ----------------
// A [M,K] row-major, B [K,N] row-major, C [M,N] row-major.
// M % 128 == 0, N % 128 == 0, K % 16 == 0. 256 threads, 128x128 tile, 8x8 micro.
__global__ __launch_bounds__(256, 2)
void sgemm_kernel(const float* __restrict__ A, const float* __restrict__ B,
                  float* __restrict__ C, int M, int N, int K,
                  const float* __restrict__ bias, int relu)
{
    __shared__ float As[16][128];
    __shared__ float Bs[16][132];

    int t  = threadIdx.x;
    int tx = t & 15, ty = t >> 4;
    int row0 = blockIdx.y * 128;
    int col0 = blockIdx.x * 128;

    int arow = t >> 2;            // 0..63
    int acol = (t & 3) << 2;      // 0,4,8,12
    int brow = t >> 5;            // 0..7
    int bcol = (t & 31) << 2;     // 0..124

    float acc[8][8];
    #pragma unroll
    for (int i = 0; i < 8; i++)
        #pragma unroll
        for (int j = 0; j < 8; j++) acc[i][j] = 0.f;

    for (int k0 = 0; k0 < K; k0 += 16) {
        float4 a0 = *(const float4*)&A[(size_t)(row0 + arow)      * K + k0 + acol];
        float4 a1 = *(const float4*)&A[(size_t)(row0 + arow + 64) * K + k0 + acol];
        float4 b0 = *(const float4*)&B[(size_t)(k0 + brow)     * N + col0 + bcol];
        float4 b1 = *(const float4*)&B[(size_t)(k0 + brow + 8) * N + col0 + bcol];

        __syncthreads();
        As[acol+0][arow]    = a0.x; As[acol+1][arow]    = a0.y;
        As[acol+2][arow]    = a0.z; As[acol+3][arow]    = a0.w;
        As[acol+0][arow+64] = a1.x; As[acol+1][arow+64] = a1.y;
        As[acol+2][arow+64] = a1.z; As[acol+3][arow+64] = a1.w;
        *(float4*)&Bs[brow][bcol]     = b0;
        *(float4*)&Bs[brow + 8][bcol] = b1;
        __syncthreads();

        #pragma unroll
        for (int kk = 0; kk < 16; kk++) {
            float4 av0 = *(const float4*)&As[kk][ty * 8];
            float4 av1 = *(const float4*)&As[kk][ty * 8 + 4];
            float4 bv0 = *(const float4*)&Bs[kk][tx * 8];
            float4 bv1 = *(const float4*)&Bs[kk][tx * 8 + 4];
            float a[8] = {av0.x, av0.y, av0.z, av0.w, av1.x, av1.y, av1.z, av1.w};
            float b[8] = {bv0.x, bv0.y, bv0.z, bv0.w, bv1.x, bv1.y, bv1.z, bv1.w};
            #pragma unroll
            for (int i = 0; i < 8; i++)
                #pragma unroll
                for (int j = 0; j < 8; j++)
                    acc[i][j] += a[i] * b[j];
        }
    }

    int col = col0 + tx * 8;
    float bv[8];
    #pragma unroll
    for (int j = 0; j < 8; j++) bv[j] = bias ? bias[col + j] : 0.f;

    #pragma unroll
    for (int i = 0; i < 8; i++) {
        int row = row0 + ty * 8 + i;
        float o[8];
        #pragma unroll
        for (int j = 0; j < 8; j++) {
            float vv = acc[i][j] + bv[j];
            o[j] = relu ? fmaxf(vv, 0.f) : vv;
        }
        *(float4*)&C[(size_t)row * N + col]     = make_float4(o[0], o[1], o[2], o[3]);
        *(float4*)&C[(size_t)row * N + col + 4] = make_float4(o[4], o[5], o[6], o[7]);
    }
}

// ---------------- attention scores: S = (q+u)@K^T + shifted (q+v)@R^T ----------------
// One block per 64x64 (i,j) tile per (b,h). Fully masked tiles (j0 > i0+575) skipped.
// BD[i,j] = (q_i+v) . r[j + 1023 - i]  on unmasked region (rel_shift closed form).
#define SP 68
#define RP 132
#define SCORES_SMEM ((3 * HDIM * SP + HDIM * RP) * (int)sizeof(float))  // 86016 B

__global__ void scores_kernel(const float* __restrict__ qkv, const float* __restrict__ rh,
                              const float* __restrict__ U, const float* __restrict__ Vh,
                              float* __restrict__ S)
{
    extern __shared__ float sm[];
    float* Qu = sm;                 // [HDIM][SP]  (d-major)
    float* Qv = Qu + HDIM * SP;
    float* Ks = Qv + HDIM * SP;
    float* Rs = Ks + HDIM * SP;     // [HDIM][RP], 128 r-rows

    int j0 = blockIdx.x * 64;
    int i0 = blockIdx.y * 64;
    if (j0 > i0 + 575) return;      // entire tile masked (j > i + MEM)
    int z = blockIdx.z, b = z >> 4, h = z & 15;
    int t = threadIdx.x;
    int rbase = j0 + 960 - i0;      // >= 0 for all surviving tiles

    {   // q (+u / +v) and k tiles
        int li = t >> 2;
        int dbase = (t & 3) << 4;
        const float* qrow = qkv + ((size_t)((i0 + li + MEMLEN) * BATCH + b)) * 3072 + h * 64;
        const float* krow = qkv + ((size_t)((j0 + li) * BATCH + b)) * 3072 + 1024 + h * 64;
        #pragma unroll
        for (int dd = 0; dd < 16; dd++) {
            int d = dbase + dd;
            float q = qrow[d];
            Qu[d * SP + li] = q + U[h * 64 + d];
            Qv[d * SP + li] = q + Vh[h * 64 + d];
            Ks[d * SP + li] = krow[d];
        }
    }
    {   // 128 r-rows [rbase, rbase+127], zero-fill OOB (those hits are masked anyway)
        int rr = t >> 1;
        int dbase = (t & 1) << 5;
        int gr = rbase + rr;
        const float* rrow = rh + (size_t)gr * DMODEL + h * 64;
        bool ok = (gr < KLENC);
        #pragma unroll
        for (int dd = 0; dd < 32; dd++) {
            int d = dbase + dd;
            Rs[d * RP + rr] = ok ? rrow[d] : 0.f;
        }
    }
    __syncthreads();

    int tx = t & 15, ty = t >> 4;
    int li0 = ty * 4, lj0 = tx * 4;
    int rb0 = lj0 + 60 - li0;       // r index = rb0 + (3 - ii + jj), in [0,126]
    float acc[4][4];
    #pragma unroll
    for (int i = 0; i < 4; i++)
        #pragma unroll
        for (int j = 0; j < 4; j++) acc[i][j] = 0.f;

    #pragma unroll 2
    for (int d = 0; d < 64; d++) {
        float4 au4 = *(const float4*)&Qu[d * SP + li0];
        float4 av4 = *(const float4*)&Qv[d * SP + li0];
        float4 kk4 = *(const float4*)&Ks[d * SP + lj0];
        float au[4] = {au4.x, au4.y, au4.z, au4.w};
        float av[4] = {av4.x, av4.y, av4.z, av4.w};
        float kk[4] = {kk4.x, kk4.y, kk4.z, kk4.w};
        float r7[7];
        #pragma unroll
        for (int s = 0; s < 7; s++) r7[s] = Rs[d * RP + rb0 + s];
        #pragma unroll
        for (int ii = 0; ii < 4; ii++)
            #pragma unroll
            for (int jj = 0; jj < 4; jj++)
                acc[ii][jj] += au[ii] * kk[jj] + av[ii] * r7[3 - ii + jj];
    }

    size_t base = ((size_t)z * QLEN + i0 + li0) * KLENC + j0 + lj0;
    #pragma unroll
    for (int ii = 0; ii < 4; ii++)
        *(float4*)&S[base + (size_t)ii * KLENC] =
            make_float4(acc[ii][0], acc[ii][1], acc[ii][2], acc[ii][3]);
}

// ---------------- masked softmax over j, in-place; masked entries -> 0 ----------------
__global__ void softmax_kernel(float* __restrict__ S)
{
    int i = blockIdx.x, z = blockIdx.y;
    float* row = S + ((size_t)z * QLEN + i) * KLENC;
    int Vn = i + 513;               // valid j: [0, i+512]
    int t = threadIdx.x;
    __shared__ float red[8];

    float vals[6];
    float m = -1e30f;
    #pragma unroll
    for (int r = 0; r < 6; r++) {
        int j = t + r * 256;
        float x = (j < Vn) ? row[j] * ATT_SCALE : -1e30f;
        vals[r] = x;
        m = fmaxf(m, x);
    }
    #pragma unroll
    for (int o = 16; o; o >>= 1) m = fmaxf(m, __shfl_xor_sync(0xffffffffu, m, o));
    if ((t & 31) == 0) red[t >> 5] = m;
    __syncthreads();
    float bm = red[0];
    #pragma unroll
    for (int w = 1; w < 8; w++) bm = fmaxf(bm, red[w]);
    __syncthreads();

    float s = 0.f;
    #pragma unroll
    for (int r = 0; r < 6; r++) {
        int j = t + r * 256;
        float p = (j < Vn) ? __expf(vals[r] - bm) : 0.f;
        vals[r] = p;
        s += p;
    }
    #pragma unroll
    for (int o = 16; o; o >>= 1) s += __shfl_xor_sync(0xffffffffu, s, o);
    if ((t & 31) == 0) red[t >> 5] = s;
    __syncthreads();
    float tot = 0.f;
    #pragma unroll
    for (int w = 0; w < 8; w++) tot += red[w];
    float inv = 1.f / tot;
    #pragma unroll
    for (int r = 0; r < 6; r++) row[t + r * 256] = vals[r] * inv;
}

// ---------------- ctx = attn @ V (k-loop bounded by causal+mem structure) ----------------
__global__ void pv_kernel(const float* __restrict__ S, const float* __restrict__ qkv,
                          float* __restrict__ ctx)
{
    __shared__ float As[64][68];   // [j][i] (attn transposed)
    __shared__ float Vs[64][68];   // [j][d]
    int i0 = blockIdx.x * 64;
    int z = blockIdx.y, b = z >> 4, h = z & 15;
    int t = threadIdx.x, tx = t & 15, ty = t >> 4;

    float acc[4][4];
    #pragma unroll
    for (int i = 0; i < 4; i++)
        #pragma unroll
        for (int j = 0; j < 4; j++) acc[i][j] = 0.f;

    int jtmax = (i0 + 575) >> 6;   // beyond this, attn == 0 exactly
    for (int jt = 0; jt <= jtmax; jt++) {
        int j0 = jt * 64;
        __syncthreads();
        {
            int li = t >> 2;
            int jb = (t & 3) << 4;
            const float* arow = S + ((size_t)z * QLEN + i0 + li) * KLENC + j0 + jb;
            const float* vrow = qkv + ((size_t)((j0 + li) * BATCH + b)) * 3072 + 2048 + h * 64 + jb;
            #pragma unroll
            for (int u4 = 0; u4 < 4; u4++) {
                float4 a = *(const float4*)&arow[u4 * 4];
                As[jb + u4 * 4 + 0][li] = a.x;
                As[jb + u4 * 4 + 1][li] = a.y;
                As[jb + u4 * 4 + 2][li] = a.z;
                As[jb + u4 * 4 + 3][li] = a.w;
                *(float4*)&Vs[li][jb + u4 * 4] = *(const float4*)&vrow[u4 * 4];
            }
        }
        __syncthreads();
        #pragma unroll 4
        for (int k = 0; k < 64; k++) {
            float4 a4 = *(const float4*)&As[k][ty * 4];
            float4 v4 = *(const float4*)&Vs[k][tx * 4];
            float a[4] = {a4.x, a4.y, a4.z, a4.w};
            float vv[4] = {v4.x, v4.y, v4.z, v4.w};
            #pragma unroll
            for (int ii = 0; ii < 4; ii++)
                #pragma unroll
                for (int jj = 0; jj < 4; jj++)
                    acc[ii][jj] += a[ii] * vv[jj];
        }
    }

    #pragma unroll
    for (int ii = 0; ii < 4; ii++) {
        size_t o = ((size_t)(i0 + ty * 4 + ii) * BATCH + b) * DMODEL + h * 64 + tx * 4;
        *(float4*)&ctx[o] = make_float4(acc[ii][0], acc[ii][1], acc[ii][2], acc[ii][3]);
    }
}

// ---------------- layernorm(out = LN(a + b) * g + beta) ----------------
__device__ __forceinline__ float block_sum256(float v, float* red)
{
    #pragma unroll
    for (int o = 16; o; o >>= 1) v += __shfl_xor_sync(0xffffffffu, v, o);
    if ((threadIdx.x & 31) == 0) red[threadIdx.x >> 5] = v;
    __syncthreads();
    float s = 0.f;
    #pragma unroll
    for (int w = 0; w < 8; w++) s += red[w];
    __syncthreads();
    return s;
}

__global__ void ln_kernel(const float* __restrict__ A, const float* __restrict__ Bv,
                          const float* __restrict__ g, const float* __restrict__ be,
                          float* __restrict__ out)
{
    int row = blockIdx.x;
    int t = threadIdx.x;
    __shared__ float red[8];
    size_t base = (size_t)row * DMODEL;

    float x[4];
    float s = 0.f;
    #pragma unroll
    for (int r = 0; r < 4; r++) {
        int c = t + r * 256;
        x[r] = A[base + c] + Bv[base + c];
        s += x[r];
    }
    float mean = block_sum256(s, red) * (1.f / DMODEL);

    float q = 0.f;
    #pragma unroll
    for (int r = 0; r < 4; r++) {
        float d = x[r] - mean;
        q += d * d;
    }
    float var = block_sum256(q, red) * (1.f / DMODEL);
    float rstd = rsqrtf(var + 1e-5f);

    #pragma unroll
    for (int r = 0; r < 4; r++) {
        int c = t + r * 256;
        out[base + c] = (x[r] - mean) * rstd * g[c] + be[c];
    }
}

// ---------------- host orchestration ----------------
extern "C" void kernel_launch(void* const* d_in, const int* in_sizes, int n_in,
                              void* d_out, int out_size)
{
    (void)in_sizes; (void)out_size;
    // metadata order: inputs, r, u, v, mem, attn_mask, W_qkv, W_r, W_o,
    //                 ln1_g, ln1_b, ln2_g, ln2_b, W1, b1, W2, b2
    // attn_mask is recomputed analytically; tolerate its absence.
    int off = (n_in >= 17) ? 0 : -1;
    const float* inp   = (const float*)d_in[0];
    const float* r     = (const float*)d_in[1];
    const float* u     = (const float*)d_in[2];
    const float* v     = (const float*)d_in[3];
    const float* mem   = (const float*)d_in[4];
    const float* W_qkv = (const float*)d_in[6 + off];
    const float* W_r   = (const float*)d_in[7 + off];
    const float* W_o   = (const float*)d_in[8 + off];
    const float* ln1g  = (const float*)d_in[9 + off];
    const float* ln1b  = (const float*)d_in[10 + off];
    const float* ln2g  = (const float*)d_in[11 + off];
    const float* ln2b  = (const float*)d_in[12 + off];
    const float* W1    = (const float*)d_in[13 + off];
    const float* b1    = (const float*)d_in[14 + off];
    const float* W2    = (const float*)d_in[15 + off];
    const float* b2    = (const float*)d_in[16 + off];
    float* out = (float*)d_out;

    float *cat_p, *qkv_p, *rh_p, *S_p, *ctx_p, *y_p, *x_p, *h_p, *y2_p;
    cudaGetSymbolAddress((void**)&cat_p, g_cat);
    cudaGetSymbolAddress((void**)&qkv_p, g_qkv);
    cudaGetSymbolAddress((void**)&rh_p,  g_rh);
    cudaGetSymbolAddress((void**)&S_p,   g_S);
    cudaGetSymbolAddress((void**)&ctx_p, g_ctx);
    cudaGetSymbolAddress((void**)&y_p,   g_y);
    cudaGetSymbolAddress((void**)&x_p,   g_x);
    cudaGetSymbolAddress((void**)&h_p,   g_h);
    cudaGetSymbolAddress((void**)&y2_p,  g_y2);

    cudaFuncSetAttribute(scores_kernel, cudaFuncAttributeMaxDynamicSharedMemorySize,
                         SCORES_SMEM);

    // cat = [mem; inputs]
    cudaMemcpyAsync(cat_p, mem, (size_t)MEMLEN * BATCH * DMODEL * sizeof(float),
                    cudaMemcpyDeviceToDevice);
    cudaMemcpyAsync(cat_p + (size_t)MEMLEN * BATCH * DMODEL, inp,
                    (size_t)QLEN * BATCH * DMODEL * sizeof(float),
                    cudaMemcpyDeviceToDevice);

    dim3 blk(256);
    // qkv = cat @ W_qkv   [6144 x 3072 x 1024]
    sgemm_kernel<<<dim3(3072 / 128, 6144 / 128), blk>>>(cat_p, W_qkv, qkv_p,
                                                        6144, 3072, 1024, nullptr, 0);
    // r_h = r @ W_r       [1536 x 1024 x 1024]
    sgemm_kernel<<<dim3(1024 / 128, 1536 / 128), blk>>>(r, W_r, rh_p,
                                                        1536, 1024, 1024, nullptr, 0);
    // attention scores (AC + rel-shifted BD)
    scores_kernel<<<dim3(KLENC / 64, QLEN / 64, BATCH * NHEAD), blk, SCORES_SMEM>>>(
        qkv_p, rh_p, u, v, S_p);
    // softmax (in-place, masked -> 0)
    softmax_kernel<<<dim3(QLEN, BATCH * NHEAD), blk>>>(S_p);
    // ctx = attn @ V
    pv_kernel<<<dim3(QLEN / 64, BATCH * NHEAD), blk>>>(S_p, qkv_p, ctx_p);
    // y = ctx @ W_o       [4096 x 1024 x 1024]
    sgemm_kernel<<<dim3(1024 / 128, 4096 / 128), blk>>>(ctx_p, W_o, y_p,
                                                        4096, 1024, 1024, nullptr, 0);
    // x = LN(inputs + y)
    ln_kernel<<<NROWS, 256>>>(inp, y_p, ln1g, ln1b, x_p);
    // h = relu(x @ W1 + b1)  [4096 x 4096 x 1024]
    sgemm_kernel<<<dim3(4096 / 128, 4096 / 128), blk>>>(x_p, W1, h_p,
                                                        4096, 4096, 1024, b1, 1);
    // y2 = h @ W2 + b2       [4096 x 1024 x 4096]
    sgemm_kernel<<<dim3(1024 / 128, 4096 / 128), blk>>>(h_p, W2, y2_p,
                                                        4096, 1024, 4096, b2, 0);
    // out = LN(x + y2)
    ln_kernel<<<NROWS, 256>>>(x_p, y2_p, ln2g, ln2b, out);
}

// round 4
// speedup vs baseline: 1.4225x; 1.4225x over previous
#include <cuda_runtime.h>
#include <cstdint>
#include <math.h>

// ---------------- problem constants ----------------
#define QLEN    1024
#define BATCH   4
#define DMODEL  1024
#define NHEAD   16
#define HDIM    64
#define MEMLEN  512
#define KLENC   1536
#define MLPD    4096
#define ATT_SCALE 0.125f
#define NROWS   4096
#define KROWS   6144

// ---------------- scratch (device globals; allocation-free) ----------------
__device__ __align__(16) float g_cat[(size_t)KROWS * DMODEL];
__device__ __align__(16) float g_qkv[(size_t)KROWS * 3 * DMODEL];
__device__ __align__(16) float g_rh [(size_t)KLENC * DMODEL];
__device__ __align__(16) float g_S  [(size_t)BATCH * NHEAD * QLEN * KLENC];
__device__ __align__(16) float g_ctx[(size_t)NROWS * DMODEL];
__device__ __align__(16) float g_y  [(size_t)NROWS * DMODEL];
__device__ __align__(16) float g_x  [(size_t)NROWS * DMODEL];
__device__ __align__(16) float g_h  [(size_t)NROWS * MLPD];
__device__ __align__(16) float g_y2 [(size_t)NROWS * DMODEL];
// transposed weights (B^T, [N,K] K-contiguous)
__device__ __align__(16) float g_WqkvT[(size_t)3072 * 1024];
__device__ __align__(16) float g_WrT  [(size_t)1024 * 1024];
__device__ __align__(16) float g_WoT  [(size_t)1024 * 1024];
__device__ __align__(16) float g_W1T  [(size_t)4096 * 1024];
__device__ __align__(16) float g_W2T  [(size_t)1024 * 4096];

__device__ __forceinline__ float tf32_rna(float x) {
    uint32_t u;
    asm("cvt.rna.tf32.f32 %0, %1;" : "=r"(u) : "f"(x));
    return __uint_as_float(u);
}

__device__ __forceinline__ void mma_tf32(float* c, const uint32_t* a, const uint32_t* b)
{
    asm volatile(
        "mma.sync.aligned.m16n8k8.row.col.f32.tf32.tf32.f32 "
        "{%0,%1,%2,%3}, {%4,%5,%6,%7}, {%8,%9}, {%0,%1,%2,%3};"
        : "+f"(c[0]), "+f"(c[1]), "+f"(c[2]), "+f"(c[3])
        : "r"(a[0]), "r"(a[1]), "r"(a[2]), "r"(a[3]), "r"(b[0]), "r"(b[1]));
}

// ============ tf32 mma.sync GEMM: C[M,N] = A[M,K] @ Bt[N,K]^T ============
// 256 threads, 128x128x16 block tile, warp grid 2(m) x 4(n), warp tile 64x32.
// A and Bt both K-contiguous; M,N % 128 == 0, K % 16 == 0.
#define SMP 20   // smem row pitch (floats) for 16-float rows

__global__ __launch_bounds__(256, 2)
void mm_mma(const float* __restrict__ A, const float* __restrict__ Bt,
            float* __restrict__ C, int M, int N, int K,
            const float* __restrict__ bias, int relu)
{
    __shared__ float As[128 * SMP];
    __shared__ float Bs[128 * SMP];

    int t = threadIdx.x;
    int wid = t >> 5, lane = t & 31;
    int g = lane >> 2, q = lane & 3;
    int row0 = blockIdx.y * 128, col0 = blockIdx.x * 128;
    int wm = (wid >> 2) * 64, wn = (wid & 3) * 32;

    // load mapping: thread t covers row = t>>1 (0..127), kc = (t&1)*8, two float4 each
    int lrow = t >> 1, lkc = (t & 1) * 8;
    const float* Ab = A  + (size_t)(row0 + lrow) * K + lkc;
    const float* Bb = Bt + (size_t)(col0 + lrow) * K + lkc;
    float* as_dst = As + lrow * SMP + lkc;
    float* bs_dst = Bs + lrow * SMP + lkc;

    float acc[4][4][4];
    #pragma unroll
    for (int i = 0; i < 4; i++)
        #pragma unroll
        for (int j = 0; j < 4; j++)
            #pragma unroll
            for (int v = 0; v < 4; v++) acc[i][j][v] = 0.f;

    int NC = K >> 4;
    float4 pa0, pa1, pb0, pb1;
    // prefetch chunk 0
    pa0 = *(const float4*)(Ab);     pa1 = *(const float4*)(Ab + 4);
    pb0 = *(const float4*)(Bb);     pb1 = *(const float4*)(Bb + 4);

    for (int c = 0; c < NC; c++) {
        // tf32-round and commit to smem
        float4 qa0 = make_float4(tf32_rna(pa0.x), tf32_rna(pa0.y), tf32_rna(pa0.z), tf32_rna(pa0.w));
        float4 qa1 = make_float4(tf32_rna(pa1.x), tf32_rna(pa1.y), tf32_rna(pa1.z), tf32_rna(pa1.w));
        float4 qb0 = make_float4(tf32_rna(pb0.x), tf32_rna(pb0.y), tf32_rna(pb0.z), tf32_rna(pb0.w));
        float4 qb1 = make_float4(tf32_rna(pb1.x), tf32_rna(pb1.y), tf32_rna(pb1.z), tf32_rna(pb1.w));
        *(float4*)(as_dst)     = qa0;
        *(float4*)(as_dst + 4) = qa1;
        *(float4*)(bs_dst)     = qb0;
        *(float4*)(bs_dst + 4) = qb1;
        __syncthreads();

        if (c + 1 < NC) {           // prefetch next chunk
            const float* An = Ab + (c + 1) * 16;
            const float* Bn = Bb + (c + 1) * 16;
            pa0 = *(const float4*)(An);     pa1 = *(const float4*)(An + 4);
            pb0 = *(const float4*)(Bn);     pb1 = *(const float4*)(Bn + 4);
        }

        #pragma unroll
        for (int ks = 0; ks < 16; ks += 8) {
            uint32_t af[4][4], bf[4][2];
            #pragma unroll
            for (int mt = 0; mt < 4; mt++) {
                int r = wm + mt * 16 + g;
                af[mt][0] = __float_as_uint(As[r * SMP + ks + q]);
                af[mt][1] = __float_as_uint(As[(r + 8) * SMP + ks + q]);
                af[mt][2] = __float_as_uint(As[r * SMP + ks + q + 4]);
                af[mt][3] = __float_as_uint(As[(r + 8) * SMP + ks + q + 4]);
            }
            #pragma unroll
            for (int nt = 0; nt < 4; nt++) {
                int rn = wn + nt * 8 + g;
                bf[nt][0] = __float_as_uint(Bs[rn * SMP + ks + q]);
                bf[nt][1] = __float_as_uint(Bs[rn * SMP + ks + q + 4]);
            }
            #pragma unroll
            for (int mt = 0; mt < 4; mt++)
                #pragma unroll
                for (int nt = 0; nt < 4; nt++)
                    mma_tf32(acc[mt][nt], af[mt], bf[nt]);
        }
        __syncthreads();
    }

    // epilogue: c0,c1 at (row, col..col+1); c2,c3 at (row+8, same cols)
    #pragma unroll
    for (int mt = 0; mt < 4; mt++) {
        int row = row0 + wm + mt * 16 + g;
        #pragma unroll
        for (int nt = 0; nt < 4; nt++) {
            int col = col0 + wn + nt * 8 + q * 2;
            float b0 = bias ? bias[col] : 0.f;
            float b1 = bias ? bias[col + 1] : 0.f;
            float o0 = acc[mt][nt][0] + b0, o1 = acc[mt][nt][1] + b1;
            float o2 = acc[mt][nt][2] + b0, o3 = acc[mt][nt][3] + b1;
            if (relu) {
                o0 = fmaxf(o0, 0.f); o1 = fmaxf(o1, 0.f);
                o2 = fmaxf(o2, 0.f); o3 = fmaxf(o3, 0.f);
            }
            *(float2*)&C[(size_t)row * N + col]       = make_float2(o0, o1);
            *(float2*)&C[(size_t)(row + 8) * N + col] = make_float2(o2, o3);
        }
    }
}

// ---------------- weight transpose: out[c][r] = in[r][c] ----------------
__global__ void transpose_kernel(const float* __restrict__ in, float* __restrict__ outp,
                                 int R, int Ccols)
{
    __shared__ float tile[32][33];
    int c0 = blockIdx.x * 32, r0 = blockIdx.y * 32;
    int tx = threadIdx.x, ty = threadIdx.y;
    #pragma unroll
    for (int i = 0; i < 32; i += 8)
        tile[ty + i][tx] = in[(size_t)(r0 + ty + i) * Ccols + c0 + tx];
    __syncthreads();
    #pragma unroll
    for (int i = 0; i < 32; i += 8)
        outp[(size_t)(c0 + ty + i) * R + r0 + tx] = tile[tx][ty + i];
}

// ---------------- attention scores ----------------
#define SP 68
#define RP 132
#define SCORES_SMEM ((3 * HDIM * SP + HDIM * RP) * (int)sizeof(float))

__global__ void scores_kernel(const float* __restrict__ qkv, const float* __restrict__ rh,
                              const float* __restrict__ U, const float* __restrict__ Vh,
                              float* __restrict__ S)
{
    extern __shared__ float sm[];
    float* Qu = sm;
    float* Qv = Qu + HDIM * SP;
    float* Ks = Qv + HDIM * SP;
    float* Rs = Ks + HDIM * SP;

    int j0 = blockIdx.x * 64;
    int i0 = blockIdx.y * 64;
    if (j0 > i0 + 575) return;
    int z = blockIdx.z, b = z >> 4, h = z & 15;
    int t = threadIdx.x;
    int rbase = j0 + 960 - i0;

    {
        int li = t >> 2;
        int dbase = (t & 3) << 4;
        const float* qrow = qkv + ((size_t)((i0 + li + MEMLEN) * BATCH + b)) * 3072 + h * 64;
        const float* krow = qkv + ((size_t)((j0 + li) * BATCH + b)) * 3072 + 1024 + h * 64;
        #pragma unroll
        for (int dd = 0; dd < 16; dd++) {
            int d = dbase + dd;
            float q = qrow[d];
            Qu[d * SP + li] = q + U[h * 64 + d];
            Qv[d * SP + li] = q + Vh[h * 64 + d];
            Ks[d * SP + li] = krow[d];
        }
    }
    {
        int rr = t >> 1;
        int dbase = (t & 1) << 5;
        int gr = rbase + rr;
        const float* rrow = rh + (size_t)gr * DMODEL + h * 64;
        bool ok = (gr < KLENC);
        #pragma unroll
        for (int dd = 0; dd < 32; dd++) {
            int d = dbase + dd;
            Rs[d * RP + rr] = ok ? rrow[d] : 0.f;
        }
    }
    __syncthreads();

    int tx = t & 15, ty = t >> 4;
    int li0 = ty * 4, lj0 = tx * 4;
    int rb0 = lj0 + 60 - li0;
    float acc[4][4];
    #pragma unroll
    for (int i = 0; i < 4; i++)
        #pragma unroll
        for (int j = 0; j < 4; j++) acc[i][j] = 0.f;

    #pragma unroll 2
    for (int d = 0; d < 64; d++) {
        float4 au4 = *(const float4*)&Qu[d * SP + li0];
        float4 av4 = *(const float4*)&Qv[d * SP + li0];
        float4 kk4 = *(const float4*)&Ks[d * SP + lj0];
        float au[4] = {au4.x, au4.y, au4.z, au4.w};
        float av[4] = {av4.x, av4.y, av4.z, av4.w};
        float kk[4] = {kk4.x, kk4.y, kk4.z, kk4.w};
        float r7[7];
        #pragma unroll
        for (int s = 0; s < 7; s++) r7[s] = Rs[d * RP + rb0 + s];
        #pragma unroll
        for (int ii = 0; ii < 4; ii++)
            #pragma unroll
            for (int jj = 0; jj < 4; jj++)
                acc[ii][jj] += au[ii] * kk[jj] + av[ii] * r7[3 - ii + jj];
    }

    size_t base = ((size_t)z * QLEN + i0 + li0) * KLENC + j0 + lj0;
    #pragma unroll
    for (int ii = 0; ii < 4; ii++)
        *(float4*)&S[base + (size_t)ii * KLENC] =
            make_float4(acc[ii][0], acc[ii][1], acc[ii][2], acc[ii][3]);
}

// ---------------- masked softmax ----------------
__global__ void softmax_kernel(float* __restrict__ S)
{
    int i = blockIdx.x, z = blockIdx.y;
    float* row = S + ((size_t)z * QLEN + i) * KLENC;
    int Vn = i + 513;
    int t = threadIdx.x;
    __shared__ float red[8];

    float vals[6];
    float m = -1e30f;
    #pragma unroll
    for (int r = 0; r < 6; r++) {
        int j = t + r * 256;
        float x = (j < Vn) ? row[j] * ATT_SCALE : -1e30f;
        vals[r] = x;
        m = fmaxf(m, x);
    }
    #pragma unroll
    for (int o = 16; o; o >>= 1) m = fmaxf(m, __shfl_xor_sync(0xffffffffu, m, o));
    if ((t & 31) == 0) red[t >> 5] = m;
    __syncthreads();
    float bm = red[0];
    #pragma unroll
    for (int w = 1; w < 8; w++) bm = fmaxf(bm, red[w]);
    __syncthreads();

    float s = 0.f;
    #pragma unroll
    for (int r = 0; r < 6; r++) {
        int j = t + r * 256;
        float p = (j < Vn) ? __expf(vals[r] - bm) : 0.f;
        vals[r] = p;
        s += p;
    }
    #pragma unroll
    for (int o = 16; o; o >>= 1) s += __shfl_xor_sync(0xffffffffu, s, o);
    if ((t & 31) == 0) red[t >> 5] = s;
    __syncthreads();
    float tot = 0.f;
    #pragma unroll
    for (int w = 0; w < 8; w++) tot += red[w];
    float inv = 1.f / tot;
    #pragma unroll
    for (int r = 0; r < 6; r++) row[t + r * 256] = vals[r] * inv;
}

// ---------------- ctx = attn @ V ----------------
__global__ void pv_kernel(const float* __restrict__ S, const float* __restrict__ qkv,
                          float* __restrict__ ctx)
{
    __shared__ float As[64][68];
    __shared__ float Vs[64][68];
    int i0 = blockIdx.x * 64;
    int z = blockIdx.y, b = z >> 4, h = z & 15;
    int t = threadIdx.x, tx = t & 15, ty = t >> 4;

    float acc[4][4];
    #pragma unroll
    for (int i = 0; i < 4; i++)
        #pragma unroll
        for (int j = 0; j < 4; j++) acc[i][j] = 0.f;

    int jtmax = (i0 + 575) >> 6;
    for (int jt = 0; jt <= jtmax; jt++) {
        int j0 = jt * 64;
        __syncthreads();
        {
            int li = t >> 2;
            int jb = (t & 3) << 4;
            const float* arow = S + ((size_t)z * QLEN + i0 + li) * KLENC + j0 + jb;
            const float* vrow = qkv + ((size_t)((j0 + li) * BATCH + b)) * 3072 + 2048 + h * 64 + jb;
            #pragma unroll
            for (int u4 = 0; u4 < 4; u4++) {
                float4 a = *(const float4*)&arow[u4 * 4];
                As[jb + u4 * 4 + 0][li] = a.x;
                As[jb + u4 * 4 + 1][li] = a.y;
                As[jb + u4 * 4 + 2][li] = a.z;
                As[jb + u4 * 4 + 3][li] = a.w;
                *(float4*)&Vs[li][jb + u4 * 4] = *(const float4*)&vrow[u4 * 4];
            }
        }
        __syncthreads();
        #pragma unroll 4
        for (int k = 0; k < 64; k++) {
            float4 a4 = *(const float4*)&As[k][ty * 4];
            float4 v4 = *(const float4*)&Vs[k][tx * 4];
            float a[4] = {a4.x, a4.y, a4.z, a4.w};
            float vv[4] = {v4.x, v4.y, v4.z, v4.w};
            #pragma unroll
            for (int ii = 0; ii < 4; ii++)
                #pragma unroll
                for (int jj = 0; jj < 4; jj++)
                    acc[ii][jj] += a[ii] * vv[jj];
        }
    }

    #pragma unroll
    for (int ii = 0; ii < 4; ii++) {
        size_t o = ((size_t)(i0 + ty * 4 + ii) * BATCH + b) * DMODEL + h * 64 + tx * 4;
        *(float4*)&ctx[o] = make_float4(acc[ii][0], acc[ii][1], acc[ii][2], acc[ii][3]);
    }
}

// ---------------- layernorm ----------------
__device__ __forceinline__ float block_sum256(float v, float* red)
{
    #pragma unroll
    for (int o = 16; o; o >>= 1) v += __shfl_xor_sync(0xffffffffu, v, o);
    if ((threadIdx.x & 31) == 0) red[threadIdx.x >> 5] = v;
    __syncthreads();
    float s = 0.f;
    #pragma unroll
    for (int w = 0; w < 8; w++) s += red[w];
    __syncthreads();
    return s;
}

__global__ void ln_kernel(const float* __restrict__ A, const float* __restrict__ Bv,
                          const float* __restrict__ g, const float* __restrict__ be,
                          float* __restrict__ out)
{
    int row = blockIdx.x;
    int t = threadIdx.x;
    __shared__ float red[8];
    size_t base = (size_t)row * DMODEL;

    float x[4];
    float s = 0.f;
    #pragma unroll
    for (int r = 0; r < 4; r++) {
        int c = t + r * 256;
        x[r] = A[base + c] + Bv[base + c];
        s += x[r];
    }
    float mean = block_sum256(s, red) * (1.f / DMODEL);

    float q = 0.f;
    #pragma unroll
    for (int r = 0; r < 4; r++) {
        float d = x[r] - mean;
        q += d * d;
    }
    float var = block_sum256(q, red) * (1.f / DMODEL);
    float rstd = rsqrtf(var + 1e-5f);

    #pragma unroll
    for (int r = 0; r < 4; r++) {
        int c = t + r * 256;
        out[base + c] = (x[r] - mean) * rstd * g[c] + be[c];
    }
}

// ---------------- host orchestration ----------------
extern "C" void kernel_launch(void* const* d_in, const int* in_sizes, int n_in,
                              void* d_out, int out_size)
{
    (void)in_sizes; (void)out_size;
    int off = (n_in >= 17) ? 0 : -1;
    const float* inp   = (const float*)d_in[0];
    const float* r     = (const float*)d_in[1];
    const float* u     = (const float*)d_in[2];
    const float* v     = (const float*)d_in[3];
    const float* mem   = (const float*)d_in[4];
    const float* W_qkv = (const float*)d_in[6 + off];
    const float* W_r   = (const float*)d_in[7 + off];
    const float* W_o   = (const float*)d_in[8 + off];
    const float* ln1g  = (const float*)d_in[9 + off];
    const float* ln1b  = (const float*)d_in[10 + off];
    const float* ln2g  = (const float*)d_in[11 + off];
    const float* ln2b  = (const float*)d_in[12 + off];
    const float* W1    = (const float*)d_in[13 + off];
    const float* b1    = (const float*)d_in[14 + off];
    const float* W2    = (const float*)d_in[15 + off];
    const float* b2    = (const float*)d_in[16 + off];
    float* out = (float*)d_out;

    float *cat_p, *qkv_p, *rh_p, *S_p, *ctx_p, *y_p, *x_p, *h_p, *y2_p;
    float *WqkvT_p, *WrT_p, *WoT_p, *W1T_p, *W2T_p;
    cudaGetSymbolAddress((void**)&cat_p, g_cat);
    cudaGetSymbolAddress((void**)&qkv_p, g_qkv);
    cudaGetSymbolAddress((void**)&rh_p,  g_rh);
    cudaGetSymbolAddress((void**)&S_p,   g_S);
    cudaGetSymbolAddress((void**)&ctx_p, g_ctx);
    cudaGetSymbolAddress((void**)&y_p,   g_y);
    cudaGetSymbolAddress((void**)&x_p,   g_x);
    cudaGetSymbolAddress((void**)&h_p,   g_h);
    cudaGetSymbolAddress((void**)&y2_p,  g_y2);
    cudaGetSymbolAddress((void**)&WqkvT_p, g_WqkvT);
    cudaGetSymbolAddress((void**)&WrT_p,   g_WrT);
    cudaGetSymbolAddress((void**)&WoT_p,   g_WoT);
    cudaGetSymbolAddress((void**)&W1T_p,   g_W1T);
    cudaGetSymbolAddress((void**)&W2T_p,   g_W2T);

    cudaFuncSetAttribute(scores_kernel, cudaFuncAttributeMaxDynamicSharedMemorySize, SCORES_SMEM);

    // cat = [mem; inputs]
    cudaMemcpyAsync(cat_p, mem, (size_t)MEMLEN * BATCH * DMODEL * sizeof(float),
                    cudaMemcpyDeviceToDevice);
    cudaMemcpyAsync(cat_p + (size_t)MEMLEN * BATCH * DMODEL, inp,
                    (size_t)QLEN * BATCH * DMODEL * sizeof(float),
                    cudaMemcpyDeviceToDevice);

    // weight transposes (B^T, K-contiguous for the mma B operand)
    dim3 tb(32, 8);
    transpose_kernel<<<dim3(3072/32, 1024/32), tb>>>(W_qkv, WqkvT_p, 1024, 3072);
    transpose_kernel<<<dim3(1024/32, 1024/32), tb>>>(W_r,   WrT_p,   1024, 1024);
    transpose_kernel<<<dim3(1024/32, 1024/32), tb>>>(W_o,   WoT_p,   1024, 1024);
    transpose_kernel<<<dim3(4096/32, 1024/32), tb>>>(W1,    W1T_p,   1024, 4096);
    transpose_kernel<<<dim3(1024/32, 4096/32), tb>>>(W2,    W2T_p,   4096, 1024);

    dim3 blk(256);
    // qkv = cat @ W_qkv   [6144 x 3072 x 1024]
    mm_mma<<<dim3(3072/128, 6144/128), blk>>>(cat_p, WqkvT_p, qkv_p,
                                              6144, 3072, 1024, nullptr, 0);
    // r_h = r @ W_r       [1536 x 1024 x 1024]
    mm_mma<<<dim3(1024/128, 1536/128), blk>>>(r, WrT_p, rh_p,
                                              1536, 1024, 1024, nullptr, 0);
    // attention scores
    scores_kernel<<<dim3(KLENC/64, QLEN/64, BATCH*NHEAD), blk, SCORES_SMEM>>>(
        qkv_p, rh_p, u, v, S_p);
    softmax_kernel<<<dim3(QLEN, BATCH*NHEAD), blk>>>(S_p);
    pv_kernel<<<dim3(QLEN/64, BATCH*NHEAD), blk>>>(S_p, qkv_p, ctx_p);
    // y = ctx @ W_o       [4096 x 1024 x 1024]
    mm_mma<<<dim3(1024/128, 4096/128), blk>>>(ctx_p, WoT_p, y_p,
                                              4096, 1024, 1024, nullptr, 0);
    ln_kernel<<<NROWS, 256>>>(inp, y_p, ln1g, ln1b, x_p);
    // h = relu(x @ W1 + b1)  [4096 x 4096 x 1024]
    mm_mma<<<dim3(4096/128, 4096/128), blk>>>(x_p, W1T_p, h_p,
                                              4096, 4096, 1024, b1, 1);
    // y2 = h @ W2 + b2       [4096 x 1024 x 4096]
    mm_mma<<<dim3(1024/128, 4096/128), blk>>>(h_p, W2T_p, y2_p,
                                              4096, 1024, 4096, b2, 0);
    ln_kernel<<<NROWS, 256>>>(x_p, y2_p, ln2g, ln2b, out);
}

// round 5
// speedup vs baseline: 2.5527x; 1.7945x over previous
#include <cuda_runtime.h>
#include <cstdint>
#include <math.h>

// ---------------- problem constants ----------------
#define QLEN    1024
#define BATCH   4
#define DMODEL  1024
#define NHEAD   16
#define HDIM    64
#define MEMLEN  512
#define KLENC   1536
#define MLPD    4096
#define ATT_SCALE 0.125f
#define NROWS   4096
#define KROWS   6144

// ---------------- scratch (device globals; allocation-free) ----------------
__device__ __align__(16) float g_cat[(size_t)KROWS * DMODEL];
__device__ __align__(16) float g_qkv[(size_t)KROWS * 3 * DMODEL];
__device__ __align__(16) float g_rh [(size_t)KLENC * DMODEL];
__device__ __align__(16) float g_S  [(size_t)64 * QLEN * KLENC];   // AC, then attn (in-place)
__device__ __align__(16) float g_BD [(size_t)64 * QLEN * KLENC];   // BD unshifted
__device__ __align__(16) float g_Qu [(size_t)64 * QLEN * HDIM];
__device__ __align__(16) float g_Qv [(size_t)64 * QLEN * HDIM];
__device__ __align__(16) float g_ctx[(size_t)NROWS * DMODEL];
__device__ __align__(16) float g_y  [(size_t)NROWS * DMODEL];
__device__ __align__(16) float g_x  [(size_t)NROWS * DMODEL];
__device__ __align__(16) float g_h  [(size_t)NROWS * MLPD];
__device__ __align__(16) float g_y2 [(size_t)NROWS * DMODEL];
__device__ __align__(16) float g_WqkvT[(size_t)3072 * 1024];
__device__ __align__(16) float g_WrT  [(size_t)1024 * 1024];
__device__ __align__(16) float g_WoT  [(size_t)1024 * 1024];
__device__ __align__(16) float g_W1T  [(size_t)4096 * 1024];
__device__ __align__(16) float g_W2T  [(size_t)1024 * 4096];

// ---------------- helpers ----------------
__device__ __forceinline__ uint32_t smem_u32(const void* p) {
    uint32_t a;
    asm("{ .reg .u64 t; cvta.to.shared.u64 t, %1; cvt.u32.u64 %0, t; }" : "=r"(a) : "l"(p));
    return a;
}
__device__ __forceinline__ uint32_t tf32u(float x) {
    uint32_t u;
    asm("cvt.rna.tf32.f32 %0, %1;" : "=r"(u) : "f"(x));
    return u;
}
__device__ __forceinline__ void cpa16(uint32_t s, const void* g) {
    asm volatile("cp.async.cg.shared.global [%0], [%1], 16;" :: "r"(s), "l"(g));
}
__device__ __forceinline__ void cpcommit() {
    asm volatile("cp.async.commit_group;" ::: "memory");
}
__device__ __forceinline__ void mma_tf32(float* c, const uint32_t* a, const uint32_t* b)
{
    asm volatile(
        "mma.sync.aligned.m16n8k8.row.col.f32.tf32.tf32.f32 "
        "{%0,%1,%2,%3}, {%4,%5,%6,%7}, {%8,%9}, {%0,%1,%2,%3};"
        : "+f"(c[0]), "+f"(c[1]), "+f"(c[2]), "+f"(c[3])
        : "r"(a[0]), "r"(a[1]), "r"(a[2]), "r"(a[3]), "r"(b[0]), "r"(b[1]));
}

// ============ batched/strided tf32 GEMM: C[M,N] = A[M,K] @ B[N,K]^T ============
// 256 threads, 128x128x16 tile, 3-stage cp.async ring, 1 syncthreads/chunk.
// Per-z (blockIdx.z) operand offsets: base + (z>>4)*s?b + (z&15)*s?h.
#define SMP 20
#define STG_F (2 * 128 * SMP)          // floats per stage (A + B)
#define MM_SMEM (3 * STG_F * 4)        // 61440 bytes

__global__ __launch_bounds__(256, 2)
void mm_mma(const float* __restrict__ A, const float* __restrict__ B, float* __restrict__ C,
            int M, int N, int K, int lda, int ldb, int ldc,
            long sAb, long sAh, long sBb, long sBh, long sCb, long sCh,
            const float* __restrict__ bias, int relu)
{
    extern __shared__ float sm_[];
    uint32_t sb = smem_u32(sm_);
    int t = threadIdx.x, wid = t >> 5, lane = t & 31, g = lane >> 2, q = lane & 3;
    int z = blockIdx.z, bb = z >> 4, hh = z & 15;
    const float* Az = A + (size_t)bb * sAb + (size_t)hh * sAh;
    const float* Bz = B + (size_t)bb * sBb + (size_t)hh * sBh;
    float* Cz = C + (size_t)bb * sCb + (size_t)hh * sCh;
    int row0 = blockIdx.y * 128, col0 = blockIdx.x * 128;
    int wm = (wid >> 2) * 64, wn = (wid & 3) * 32;

    int lrow = t >> 1, lkc = (t & 1) * 8;
    const float* Ag = Az + (size_t)(row0 + lrow) * lda + lkc;
    const float* Bg = Bz + (size_t)(col0 + lrow) * ldb + lkc;
    uint32_t as_s = sb + (uint32_t)((lrow * SMP + lkc) * 4);
    uint32_t bs_s = as_s + 128 * SMP * 4;

    float acc[4][4][4];
    #pragma unroll
    for (int i = 0; i < 4; i++)
        #pragma unroll
        for (int j = 0; j < 4; j++)
            #pragma unroll
            for (int v = 0; v < 4; v++) acc[i][j][v] = 0.f;

    int NC = K >> 4;
    auto issue = [&](int c) {
        uint32_t off = (uint32_t)(c % 3) * STG_F * 4;
        const float* ag = Ag + c * 16;
        const float* bg = Bg + c * 16;
        cpa16(as_s + off, ag); cpa16(as_s + off + 16, ag + 4);
        cpa16(bs_s + off, bg); cpa16(bs_s + off + 16, bg + 4);
        cpcommit();
    };
    issue(0);
    if (NC > 1) issue(1);

    for (int c = 0; c < NC; c++) {
        if (c + 1 < NC) asm volatile("cp.async.wait_group 1;" ::: "memory");
        else            asm volatile("cp.async.wait_group 0;" ::: "memory");
        __syncthreads();
        if (c + 2 < NC) issue(c + 2);

        const float* As = sm_ + (c % 3) * STG_F;
        const float* Bs = As + 128 * SMP;
        #pragma unroll
        for (int ks = 0; ks < 16; ks += 8) {
            uint32_t af[4][4], bf[4][2];
            #pragma unroll
            for (int mt = 0; mt < 4; mt++) {
                int r = wm + mt * 16 + g;
                af[mt][0] = tf32u(As[r * SMP + ks + q]);
                af[mt][1] = tf32u(As[(r + 8) * SMP + ks + q]);
                af[mt][2] = tf32u(As[r * SMP + ks + q + 4]);
                af[mt][3] = tf32u(As[(r + 8) * SMP + ks + q + 4]);
            }
            #pragma unroll
            for (int nt = 0; nt < 4; nt++) {
                int rn = wn + nt * 8 + g;
                bf[nt][0] = tf32u(Bs[rn * SMP + ks + q]);
                bf[nt][1] = tf32u(Bs[rn * SMP + ks + q + 4]);
            }
            #pragma unroll
            for (int mt = 0; mt < 4; mt++)
                #pragma unroll
                for (int nt = 0; nt < 4; nt++)
                    mma_tf32(acc[mt][nt], af[mt], bf[nt]);
        }
    }

    #pragma unroll
    for (int mt = 0; mt < 4; mt++) {
        int row = row0 + wm + mt * 16 + g;
        #pragma unroll
        for (int nt = 0; nt < 4; nt++) {
            int col = col0 + wn + nt * 8 + q * 2;
            float b0 = bias ? bias[col] : 0.f;
            float b1 = bias ? bias[col + 1] : 0.f;
            float o0 = acc[mt][nt][0] + b0, o1 = acc[mt][nt][1] + b1;
            float o2 = acc[mt][nt][2] + b0, o3 = acc[mt][nt][3] + b1;
            if (relu) {
                o0 = fmaxf(o0, 0.f); o1 = fmaxf(o1, 0.f);
                o2 = fmaxf(o2, 0.f); o3 = fmaxf(o3, 0.f);
            }
            *(float2*)&Cz[(size_t)row * ldc + col]       = make_float2(o0, o1);
            *(float2*)&Cz[(size_t)(row + 8) * ldc + col] = make_float2(o2, o3);
        }
    }
}

// ============ PV: ctx = attn @ V, mma, 128x64 tile, K bounded by causal mask ============
#define VP 72
#define PV_STG_F (128 * SMP + 16 * VP)
#define PV_SMEM (3 * PV_STG_F * 4)

__global__ __launch_bounds__(256, 2)
void pv_mma(const float* __restrict__ S, const float* __restrict__ qkv,
            float* __restrict__ ctx)
{
    extern __shared__ float sm_[];
    uint32_t sb = smem_u32(sm_);
    int t = threadIdx.x, wid = t >> 5, lane = t & 31, g = lane >> 2, q = lane & 3;
    int i0 = blockIdx.x * 128;
    int z = blockIdx.y, bb = z >> 4, hh = z & 15;
    int wm = (wid >> 1) * 32, wn = (wid & 1) * 32;

    const float* Arow = S + ((size_t)z * QLEN + i0 + (t >> 1)) * KLENC + (t & 1) * 8;
    uint32_t as_s = sb + (uint32_t)(((t >> 1) * SMP + (t & 1) * 8) * 4);
    // V loader: threads 0..127
    int vrow = (t & 127) >> 3, vcol = (t & 7) * 8;
    uint32_t vs_s = sb + (uint32_t)((128 * SMP + vrow * VP + vcol) * 4);

    float acc[2][4][4];
    #pragma unroll
    for (int i = 0; i < 2; i++)
        #pragma unroll
        for (int j = 0; j < 4; j++)
            #pragma unroll
            for (int v = 0; v < 4; v++) acc[i][j][v] = 0.f;

    int jlim = i0 + 640; if (jlim > KLENC) jlim = KLENC;
    int NC = jlim >> 4;

    auto issue = [&](int c) {
        uint32_t off = (uint32_t)(c % 3) * PV_STG_F * 4;
        const float* ag = Arow + c * 16;
        cpa16(as_s + off, ag); cpa16(as_s + off + 16, ag + 4);
        if (t < 128) {
            const float* vg = qkv + ((size_t)((c * 16 + vrow) * 4 + bb)) * 3072 + 2048 + hh * 64 + vcol;
            cpa16(vs_s + off, vg); cpa16(vs_s + off + 16, vg + 4);
        }
        cpcommit();
    };
    issue(0);
    if (NC > 1) issue(1);

    for (int c = 0; c < NC; c++) {
        if (c + 1 < NC) asm volatile("cp.async.wait_group 1;" ::: "memory");
        else            asm volatile("cp.async.wait_group 0;" ::: "memory");
        __syncthreads();
        if (c + 2 < NC) issue(c + 2);

        const float* As = sm_ + (c % 3) * PV_STG_F;
        const float* Vs = As + 128 * SMP;
        #pragma unroll
        for (int ks = 0; ks < 16; ks += 8) {
            uint32_t af[2][4], bf[4][2];
            #pragma unroll
            for (int mt = 0; mt < 2; mt++) {
                int r = wm + mt * 16 + g;
                af[mt][0] = tf32u(As[r * SMP + ks + q]);
                af[mt][1] = tf32u(As[(r + 8) * SMP + ks + q]);
                af[mt][2] = tf32u(As[r * SMP + ks + q + 4]);
                af[mt][3] = tf32u(As[(r + 8) * SMP + ks + q + 4]);
            }
            #pragma unroll
            for (int nt = 0; nt < 4; nt++) {
                int n = wn + nt * 8 + g;
                bf[nt][0] = tf32u(Vs[(ks + q) * VP + n]);
                bf[nt][1] = tf32u(Vs[(ks + q + 4) * VP + n]);
            }
            #pragma unroll
            for (int mt = 0; mt < 2; mt++)
                #pragma unroll
                for (int nt = 0; nt < 4; nt++)
                    mma_tf32(acc[mt][nt], af[mt], bf[nt]);
        }
    }

    #pragma unroll
    for (int mt = 0; mt < 2; mt++) {
        int m = i0 + wm + mt * 16 + g;
        #pragma unroll
        for (int nt = 0; nt < 4; nt++) {
            int d = wn + nt * 8 + q * 2;
            size_t o0 = ((size_t)m * 4 + bb) * 1024 + hh * 64 + d;
            size_t o1 = ((size_t)(m + 8) * 4 + bb) * 1024 + hh * 64 + d;
            *(float2*)&ctx[o0] = make_float2(acc[mt][nt][0], acc[mt][nt][1]);
            *(float2*)&ctx[o1] = make_float2(acc[mt][nt][2], acc[mt][nt][3]);
        }
    }
}

// ---------------- Qu/Qv prep: fold u,v into q heads, z-major layout ----------------
__global__ void quv_prep(const float* __restrict__ qkv, const float* __restrict__ u,
                         const float* __restrict__ v, float* __restrict__ Qu,
                         float* __restrict__ Qv)
{
    size_t idx = (size_t)blockIdx.x * 256 + threadIdx.x;   // 64*1024*64 total
    int d = idx & 63;
    size_t row = idx >> 6;
    int i = row & 1023;
    int z = row >> 10, bb = z >> 4, hh = z & 15;
    float qv = qkv[((size_t)((MEMLEN + i) * 4 + bb)) * 3072 + hh * 64 + d];
    Qu[idx] = qv + u[hh * 64 + d];
    Qv[idx] = qv + v[hh * 64 + d];
}

// ---------------- weight transpose ----------------
__global__ void transpose_kernel(const float* __restrict__ in, float* __restrict__ outp,
                                 int R, int Ccols)
{
    __shared__ float tile[32][33];
    int c0 = blockIdx.x * 32, r0 = blockIdx.y * 32;
    int tx = threadIdx.x, ty = threadIdx.y;
    #pragma unroll
    for (int i = 0; i < 32; i += 8)
        tile[ty + i][tx] = in[(size_t)(r0 + ty + i) * Ccols + c0 + tx];
    __syncthreads();
    #pragma unroll
    for (int i = 0; i < 32; i += 8)
        outp[(size_t)(c0 + ty + i) * R + r0 + tx] = tile[tx][ty + i];
}

// ---------------- fused rel-shift + mask + softmax ----------------
// attn[i,j] = softmax_j( (AC[i,j] + BD[i, j+1023-i]) * scale ), j <= i+512; else 0.
__global__ void softmax_kernel(float* __restrict__ S, const float* __restrict__ BD)
{
    int i = blockIdx.x, z = blockIdx.y;
    float* row = S + ((size_t)z * QLEN + i) * KLENC;
    const float* bdrow = BD + ((size_t)z * QLEN + i) * KLENC + (1023 - i);
    int Vn = i + 513;
    int t = threadIdx.x;
    __shared__ float red[8];

    float vals[6];
    float m = -1e30f;
    #pragma unroll
    for (int r = 0; r < 6; r++) {
        int j = t + r * 256;
        float x = (j < Vn) ? (row[j] + bdrow[j]) * ATT_SCALE : -1e30f;
        vals[r] = x;
        m = fmaxf(m, x);
    }
    #pragma unroll
    for (int o = 16; o; o >>= 1) m = fmaxf(m, __shfl_xor_sync(0xffffffffu, m, o));
    if ((t & 31) == 0) red[t >> 5] = m;
    __syncthreads();
    float bm = red[0];
    #pragma unroll
    for (int w = 1; w < 8; w++) bm = fmaxf(bm, red[w]);
    __syncthreads();

    float s = 0.f;
    #pragma unroll
    for (int r = 0; r < 6; r++) {
        int j = t + r * 256;
        float p = (j < Vn) ? __expf(vals[r] - bm) : 0.f;
        vals[r] = p;
        s += p;
    }
    #pragma unroll
    for (int o = 16; o; o >>= 1) s += __shfl_xor_sync(0xffffffffu, s, o);
    if ((t & 31) == 0) red[t >> 5] = s;
    __syncthreads();
    float tot = 0.f;
    #pragma unroll
    for (int w = 0; w < 8; w++) tot += red[w];
    float inv = 1.f / tot;
    #pragma unroll
    for (int r = 0; r < 6; r++) row[t + r * 256] = vals[r] * inv;
}

// ---------------- layernorm ----------------
__device__ __forceinline__ float block_sum256(float v, float* red)
{
    #pragma unroll
    for (int o = 16; o; o >>= 1) v += __shfl_xor_sync(0xffffffffu, v, o);
    if ((threadIdx.x & 31) == 0) red[threadIdx.x >> 5] = v;
    __syncthreads();
    float s = 0.f;
    #pragma unroll
    for (int w = 0; w < 8; w++) s += red[w];
    __syncthreads();
    return s;
}

__global__ void ln_kernel(const float* __restrict__ A, const float* __restrict__ Bv,
                          const float* __restrict__ g, const float* __restrict__ be,
                          float* __restrict__ out)
{
    int row = blockIdx.x;
    int t = threadIdx.x;
    __shared__ float red[8];
    size_t base = (size_t)row * DMODEL;

    float x[4];
    float s = 0.f;
    #pragma unroll
    for (int r = 0; r < 4; r++) {
        int c = t + r * 256;
        x[r] = A[base + c] + Bv[base + c];
        s += x[r];
    }
    float mean = block_sum256(s, red) * (1.f / DMODEL);

    float q = 0.f;
    #pragma unroll
    for (int r = 0; r < 4; r++) {
        float d = x[r] - mean;
        q += d * d;
    }
    float var = block_sum256(q, red) * (1.f / DMODEL);
    float rstd = rsqrtf(var + 1e-5f);

    #pragma unroll
    for (int r = 0; r < 4; r++) {
        int c = t + r * 256;
        out[base + c] = (x[r] - mean) * rstd * g[c] + be[c];
    }
}

// ---------------- host orchestration ----------------
extern "C" void kernel_launch(void* const* d_in, const int* in_sizes, int n_in,
                              void* d_out, int out_size)
{
    (void)in_sizes; (void)out_size;
    int off = (n_in >= 17) ? 0 : -1;
    const float* inp   = (const float*)d_in[0];
    const float* r     = (const float*)d_in[1];
    const float* u     = (const float*)d_in[2];
    const float* v     = (const float*)d_in[3];
    const float* mem   = (const float*)d_in[4];
    const float* W_qkv = (const float*)d_in[6 + off];
    const float* W_r   = (const float*)d_in[7 + off];
    const float* W_o   = (const float*)d_in[8 + off];
    const float* ln1g  = (const float*)d_in[9 + off];
    const float* ln1b  = (const float*)d_in[10 + off];
    const float* ln2g  = (const float*)d_in[11 + off];
    const float* ln2b  = (const float*)d_in[12 + off];
    const float* W1    = (const float*)d_in[13 + off];
    const float* b1    = (const float*)d_in[14 + off];
    const float* W2    = (const float*)d_in[15 + off];
    const float* b2    = (const float*)d_in[16 + off];
    float* out = (float*)d_out;

    float *cat_p, *qkv_p, *rh_p, *S_p, *BD_p, *Qu_p, *Qv_p, *ctx_p, *y_p, *x_p, *h_p, *y2_p;
    float *WqkvT_p, *WrT_p, *WoT_p, *W1T_p, *W2T_p;
    cudaGetSymbolAddress((void**)&cat_p, g_cat);
    cudaGetSymbolAddress((void**)&qkv_p, g_qkv);
    cudaGetSymbolAddress((void**)&rh_p,  g_rh);
    cudaGetSymbolAddress((void**)&S_p,   g_S);
    cudaGetSymbolAddress((void**)&BD_p,  g_BD);
    cudaGetSymbolAddress((void**)&Qu_p,  g_Qu);
    cudaGetSymbolAddress((void**)&Qv_p,  g_Qv);
    cudaGetSymbolAddress((void**)&ctx_p, g_ctx);
    cudaGetSymbolAddress((void**)&y_p,   g_y);
    cudaGetSymbolAddress((void**)&x_p,   g_x);
    cudaGetSymbolAddress((void**)&h_p,   g_h);
    cudaGetSymbolAddress((void**)&y2_p,  g_y2);
    cudaGetSymbolAddress((void**)&WqkvT_p, g_WqkvT);
    cudaGetSymbolAddress((void**)&WrT_p,   g_WrT);
    cudaGetSymbolAddress((void**)&WoT_p,   g_WoT);
    cudaGetSymbolAddress((void**)&W1T_p,   g_W1T);
    cudaGetSymbolAddress((void**)&W2T_p,   g_W2T);

    cudaFuncSetAttribute(mm_mma, cudaFuncAttributeMaxDynamicSharedMemorySize, MM_SMEM);
    cudaFuncSetAttribute(pv_mma, cudaFuncAttributeMaxDynamicSharedMemorySize, PV_SMEM);

    // cat = [mem; inputs]
    cudaMemcpyAsync(cat_p, mem, (size_t)MEMLEN * BATCH * DMODEL * sizeof(float),
                    cudaMemcpyDeviceToDevice);
    cudaMemcpyAsync(cat_p + (size_t)MEMLEN * BATCH * DMODEL, inp,
                    (size_t)QLEN * BATCH * DMODEL * sizeof(float),
                    cudaMemcpyDeviceToDevice);

    // weight transposes (B^T, K-contiguous)
    dim3 tb(32, 8);
    transpose_kernel<<<dim3(3072/32, 1024/32), tb>>>(W_qkv, WqkvT_p, 1024, 3072);
    transpose_kernel<<<dim3(1024/32, 1024/32), tb>>>(W_r,   WrT_p,   1024, 1024);
    transpose_kernel<<<dim3(1024/32, 1024/32), tb>>>(W_o,   WoT_p,   1024, 1024);
    transpose_kernel<<<dim3(4096/32, 1024/32), tb>>>(W1,    W1T_p,   1024, 4096);
    transpose_kernel<<<dim3(1024/32, 4096/32), tb>>>(W2,    W2T_p,   4096, 1024);

    dim3 blk(256);
    // qkv = cat @ W_qkv   [6144 x 3072 x 1024]
    mm_mma<<<dim3(3072/128, 6144/128, 1), blk, MM_SMEM>>>(
        cat_p, WqkvT_p, qkv_p, 6144, 3072, 1024, 1024, 1024, 3072,
        0, 0, 0, 0, 0, 0, nullptr, 0);
    // r_h = r @ W_r       [1536 x 1024 x 1024]
    mm_mma<<<dim3(1024/128, 1536/128, 1), blk, MM_SMEM>>>(
        r, WrT_p, rh_p, 1536, 1024, 1024, 1024, 1024, 1024,
        0, 0, 0, 0, 0, 0, nullptr, 0);
    // Qu/Qv prep
    quv_prep<<<(64 * QLEN * HDIM) / 256, 256>>>(qkv_p, u, v, Qu_p, Qv_p);
    // AC[z] = Qu @ K^T  [1024 x 1536 x 64], batched over z=64
    mm_mma<<<dim3(1536/128, 1024/128, 64), blk, MM_SMEM>>>(
        Qu_p, qkv_p + 1024, S_p, 1024, 1536, 64, 64, 12288, 1536,
        (long)16*1024*64, (long)1024*64, 3072, 64,
        (long)16*1024*1536, (long)1024*1536, nullptr, 0);
    // BD[z] = Qv @ rh^T [1024 x 1536 x 64], batched over z=64
    mm_mma<<<dim3(1536/128, 1024/128, 64), blk, MM_SMEM>>>(
        Qv_p, rh_p, BD_p, 1024, 1536, 64, 64, 1024, 1536,
        (long)16*1024*64, (long)1024*64, 0, 64,
        (long)16*1024*1536, (long)1024*1536, nullptr, 0);
    // fused rel-shift + mask + softmax (attn in-place in S)
    softmax_kernel<<<dim3(QLEN, 64), blk>>>(S_p, BD_p);
    // ctx = attn @ V
    pv_mma<<<dim3(QLEN/128, 64), blk, PV_SMEM>>>(S_p, qkv_p, ctx_p);
    // y = ctx @ W_o       [4096 x 1024 x 1024]
    mm_mma<<<dim3(1024/128, 4096/128, 1), blk, MM_SMEM>>>(
        ctx_p, WoT_p, y_p, 4096, 1024, 1024, 1024, 1024, 1024,
        0, 0, 0, 0, 0, 0, nullptr, 0);
    ln_kernel<<<NROWS, 256>>>(inp, y_p, ln1g, ln1b, x_p);
    // h = relu(x @ W1 + b1)  [4096 x 4096 x 1024]
    mm_mma<<<dim3(4096/128, 4096/128, 1), blk, MM_SMEM>>>(
        x_p, W1T_p, h_p, 4096, 4096, 1024, 1024, 1024, 4096,
        0, 0, 0, 0, 0, 0, b1, 1);
    // y2 = h @ W2 + b2       [4096 x 1024 x 4096]
    mm_mma<<<dim3(1024/128, 4096/128, 1), blk, MM_SMEM>>>(
        h_p, W2T_p, y2_p, 4096, 1024, 4096, 4096, 4096, 1024,
        0, 0, 0, 0, 0, 0, b2, 0);
    ln_kernel<<<NROWS, 256>>>(x_p, y2_p, ln2g, ln2b, out);
}

// round 6
// speedup vs baseline: 2.6473x; 1.0371x over previous
#include <cuda_runtime.h>
#include <cstdint>
#include <math.h>

// ---------------- problem constants ----------------
#define QLEN    1024
#define BATCH   4
#define DMODEL  1024
#define NHEAD   16
#define HDIM    64
#define MEMLEN  512
#define KLENC   1536
#define MLPD    4096
#define ATT_SCALE 0.125f
#define NROWS   4096
#define KROWS   6144

// ---------------- scratch (device globals; allocation-free) ----------------
__device__ __align__(16) float g_cat[(size_t)KROWS * DMODEL];
__device__ __align__(16) float g_qkv[(size_t)KROWS * 3 * DMODEL];
__device__ __align__(16) float g_rh [(size_t)KLENC * DMODEL];
__device__ __align__(16) float g_S  [(size_t)64 * QLEN * KLENC];   // unnormalized probs P
__device__ __align__(16) float g_BD [(size_t)64 * QLEN * KLENC];   // BD unshifted
__device__ __align__(16) float g_Qu [(size_t)64 * QLEN * HDIM];
__device__ __align__(16) float g_Qv [(size_t)64 * QLEN * HDIM];
__device__ __align__(16) float g_rsum[(size_t)64 * QLEN];
__device__ __align__(16) float g_ctx[(size_t)NROWS * DMODEL];
__device__ __align__(16) float g_y  [(size_t)NROWS * DMODEL];
__device__ __align__(16) float g_x  [(size_t)NROWS * DMODEL];
__device__ __align__(16) float g_h  [(size_t)NROWS * MLPD];
__device__ __align__(16) float g_y2 [(size_t)NROWS * DMODEL];
__device__ __align__(16) float g_WqkvT[(size_t)3072 * 1024];
__device__ __align__(16) float g_WrT  [(size_t)1024 * 1024];
__device__ __align__(16) float g_WoT  [(size_t)1024 * 1024];
__device__ __align__(16) float g_W1T  [(size_t)4096 * 1024];
__device__ __align__(16) float g_W2T  [(size_t)1024 * 4096];

// ---------------- helpers ----------------
__device__ __forceinline__ uint32_t smem_u32(const void* p) {
    uint32_t a;
    asm("{ .reg .u64 t; cvta.to.shared.u64 t, %1; cvt.u32.u64 %0, t; }" : "=r"(a) : "l"(p));
    return a;
}
__device__ __forceinline__ uint32_t tf32u(float x) {
    uint32_t u;
    asm("cvt.rna.tf32.f32 %0, %1;" : "=r"(u) : "f"(x));
    return u;
}
__device__ __forceinline__ void cpa16(uint32_t s, const void* g) {
    asm volatile("cp.async.cg.shared.global [%0], [%1], 16;" :: "r"(s), "l"(g));
}
__device__ __forceinline__ void cpcommit() {
    asm volatile("cp.async.commit_group;" ::: "memory");
}
__device__ __forceinline__ void mma_tf32(float* c, const uint32_t* a, const uint32_t* b)
{
    asm volatile(
        "mma.sync.aligned.m16n8k8.row.col.f32.tf32.tf32.f32 "
        "{%0,%1,%2,%3}, {%4,%5,%6,%7}, {%8,%9}, {%0,%1,%2,%3};"
        : "+f"(c[0]), "+f"(c[1]), "+f"(c[2]), "+f"(c[3])
        : "r"(a[0]), "r"(a[1]), "r"(a[2]), "r"(a[3]), "r"(b[0]), "r"(b[1]));
}

#define SMP 20
#define STG_F (2 * 128 * SMP)
#define MM_SMEM (3 * STG_F * 4)

// ============ batched/strided tf32 GEMM: C[M,N] = A[M,K] @ B[N,K]^T ============
__global__ __launch_bounds__(256, 2)
void mm_mma(const float* __restrict__ A, const float* __restrict__ B, float* __restrict__ C,
            int M, int N, int K, int lda, int ldb, int ldc,
            long sAb, long sAh, long sBb, long sBh, long sCb, long sCh,
            const float* __restrict__ bias, int relu)
{
    extern __shared__ float sm_[];
    uint32_t sb = smem_u32(sm_);
    int t = threadIdx.x, wid = t >> 5, lane = t & 31, g = lane >> 2, q = lane & 3;
    int z = blockIdx.z, bb = z >> 4, hh = z & 15;
    const float* Az = A + (size_t)bb * sAb + (size_t)hh * sAh;
    const float* Bz = B + (size_t)bb * sBb + (size_t)hh * sBh;
    float* Cz = C + (size_t)bb * sCb + (size_t)hh * sCh;
    int row0 = blockIdx.y * 128, col0 = blockIdx.x * 128;
    int wm = (wid >> 2) * 64, wn = (wid & 3) * 32;

    int lrow = t >> 1, lkc = (t & 1) * 8;
    const float* Ag = Az + (size_t)(row0 + lrow) * lda + lkc;
    const float* Bg = Bz + (size_t)(col0 + lrow) * ldb + lkc;
    uint32_t as_s = sb + (uint32_t)((lrow * SMP + lkc) * 4);
    uint32_t bs_s = as_s + 128 * SMP * 4;

    float acc[4][4][4];
    #pragma unroll
    for (int i = 0; i < 4; i++)
        #pragma unroll
        for (int j = 0; j < 4; j++)
            #pragma unroll
            for (int v = 0; v < 4; v++) acc[i][j][v] = 0.f;

    int NC = K >> 4;
    auto issue = [&](int c) {
        uint32_t off = (uint32_t)(c % 3) * STG_F * 4;
        const float* ag = Ag + c * 16;
        const float* bg = Bg + c * 16;
        cpa16(as_s + off, ag); cpa16(as_s + off + 16, ag + 4);
        cpa16(bs_s + off, bg); cpa16(bs_s + off + 16, bg + 4);
        cpcommit();
    };
    issue(0);
    if (NC > 1) issue(1);

    for (int c = 0; c < NC; c++) {
        if (c + 1 < NC) asm volatile("cp.async.wait_group 1;" ::: "memory");
        else            asm volatile("cp.async.wait_group 0;" ::: "memory");
        __syncthreads();
        if (c + 2 < NC) issue(c + 2);

        const float* As = sm_ + (c % 3) * STG_F;
        const float* Bs = As + 128 * SMP;
        #pragma unroll
        for (int ks = 0; ks < 16; ks += 8) {
            uint32_t af[4][4], bf[4][2];
            #pragma unroll
            for (int mt = 0; mt < 4; mt++) {
                int r = wm + mt * 16 + g;
                af[mt][0] = tf32u(As[r * SMP + ks + q]);
                af[mt][1] = tf32u(As[(r + 8) * SMP + ks + q]);
                af[mt][2] = tf32u(As[r * SMP + ks + q + 4]);
                af[mt][3] = tf32u(As[(r + 8) * SMP + ks + q + 4]);
            }
            #pragma unroll
            for (int nt = 0; nt < 4; nt++) {
                int rn = wn + nt * 8 + g;
                bf[nt][0] = tf32u(Bs[rn * SMP + ks + q]);
                bf[nt][1] = tf32u(Bs[rn * SMP + ks + q + 4]);
            }
            #pragma unroll
            for (int mt = 0; mt < 4; mt++)
                #pragma unroll
                for (int nt = 0; nt < 4; nt++)
                    mma_tf32(acc[mt][nt], af[mt], bf[nt]);
        }
    }

    #pragma unroll
    for (int mt = 0; mt < 4; mt++) {
        int row = row0 + wm + mt * 16 + g;
        #pragma unroll
        for (int nt = 0; nt < 4; nt++) {
            int col = col0 + wn + nt * 8 + q * 2;
            float b0 = bias ? bias[col] : 0.f;
            float b1 = bias ? bias[col + 1] : 0.f;
            float o0 = acc[mt][nt][0] + b0, o1 = acc[mt][nt][1] + b1;
            float o2 = acc[mt][nt][2] + b0, o3 = acc[mt][nt][3] + b1;
            if (relu) {
                o0 = fmaxf(o0, 0.f); o1 = fmaxf(o1, 0.f);
                o2 = fmaxf(o2, 0.f); o3 = fmaxf(o3, 0.f);
            }
            *(float2*)&Cz[(size_t)row * ldc + col]       = make_float2(o0, o1);
            *(float2*)&Cz[(size_t)(row + 8) * ldc + col] = make_float2(o2, o3);
        }
    }
}

// ============ AC GEMM + fused BD-shift + mask + exp + rowsum ============
// P[i,j] = exp((Qu_i·K_j + BD[i, j+1023-i]) * scale) for j <= i+512, else 0.
// rsum[z][i] += row partials (atomics). Fully-masked tiles skipped.
__global__ __launch_bounds__(256, 2)
void ac_fused(const float* __restrict__ Qu, const float* __restrict__ qkv,
              const float* __restrict__ BD, float* __restrict__ S,
              float* __restrict__ rsum)
{
    extern __shared__ float sm_[];
    int i0 = blockIdx.y * 128, j0 = blockIdx.x * 128;
    if (j0 > i0 + 639) return;                    // tile fully masked
    uint32_t sb = smem_u32(sm_);
    int t = threadIdx.x, wid = t >> 5, lane = t & 31, g = lane >> 2, q = lane & 3;
    int z = blockIdx.z, bb = z >> 4, hh = z & 15;
    int wm = (wid >> 2) * 64, wn = (wid & 3) * 32;

    const float* Az = Qu + (size_t)z * QLEN * HDIM;
    int lrow = t >> 1, lkc = (t & 1) * 8;
    const float* Ag = Az + (size_t)(i0 + lrow) * HDIM + lkc;
    const float* Bg = qkv + ((size_t)(j0 + lrow) * 4 + bb) * 3072 + 1024 + hh * 64 + lkc;
    uint32_t as_s = sb + (uint32_t)((lrow * SMP + lkc) * 4);
    uint32_t bs_s = as_s + 128 * SMP * 4;

    float acc[4][4][4];
    #pragma unroll
    for (int i = 0; i < 4; i++)
        #pragma unroll
        for (int j = 0; j < 4; j++)
            #pragma unroll
            for (int v = 0; v < 4; v++) acc[i][j][v] = 0.f;

    auto issue = [&](int c) {
        uint32_t off = (uint32_t)(c % 3) * STG_F * 4;
        const float* ag = Ag + c * 16;
        const float* bg = Bg + c * 16;
        cpa16(as_s + off, ag); cpa16(as_s + off + 16, ag + 4);
        cpa16(bs_s + off, bg); cpa16(bs_s + off + 16, bg + 4);
        cpcommit();
    };
    issue(0); issue(1);

    #pragma unroll
    for (int c = 0; c < 4; c++) {                 // K=64
        if (c + 1 < 4) asm volatile("cp.async.wait_group 1;" ::: "memory");
        else           asm volatile("cp.async.wait_group 0;" ::: "memory");
        __syncthreads();
        if (c + 2 < 4) issue(c + 2);

        const float* As = sm_ + (c % 3) * STG_F;
        const float* Bs = As + 128 * SMP;
        #pragma unroll
        for (int ks = 0; ks < 16; ks += 8) {
            uint32_t af[4][4], bf[4][2];
            #pragma unroll
            for (int mt = 0; mt < 4; mt++) {
                int r = wm + mt * 16 + g;
                af[mt][0] = tf32u(As[r * SMP + ks + q]);
                af[mt][1] = tf32u(As[(r + 8) * SMP + ks + q]);
                af[mt][2] = tf32u(As[r * SMP + ks + q + 4]);
                af[mt][3] = tf32u(As[(r + 8) * SMP + ks + q + 4]);
            }
            #pragma unroll
            for (int nt = 0; nt < 4; nt++) {
                int rn = wn + nt * 8 + g;
                bf[nt][0] = tf32u(Bs[rn * SMP + ks + q]);
                bf[nt][1] = tf32u(Bs[rn * SMP + ks + q + 4]);
            }
            #pragma unroll
            for (int mt = 0; mt < 4; mt++)
                #pragma unroll
                for (int nt = 0; nt < 4; nt++)
                    mma_tf32(acc[mt][nt], af[mt], bf[nt]);
        }
    }

    // epilogue: add shifted BD, mask, exp, store P; per-row partial sums -> atomics
    const float* BDz = BD + (size_t)z * QLEN * KLENC;
    float* Sz = S + (size_t)z * QLEN * KLENC;
    float* rz = rsum + (size_t)z * QLEN;
    #pragma unroll
    for (int mt = 0; mt < 4; mt++) {
        int r0i = i0 + wm + mt * 16 + g;
        int r1i = r0i + 8;
        float s0 = 0.f, s1 = 0.f;
        const float* bd0 = BDz + (size_t)r0i * KLENC + (1023 - r0i);
        const float* bd1 = BDz + (size_t)r1i * KLENC + (1023 - r1i);
        #pragma unroll
        for (int nt = 0; nt < 4; nt++) {
            int col = j0 + wn + nt * 8 + q * 2;
            int v00 = (col     <= r0i + 512);
            int v01 = (col + 1 <= r0i + 512);
            int v10 = (col     <= r1i + 512);
            int v11 = (col + 1 <= r1i + 512);
            float p00 = v00 ? __expf((acc[mt][nt][0] + bd0[col])     * ATT_SCALE) : 0.f;
            float p01 = v01 ? __expf((acc[mt][nt][1] + bd0[col + 1]) * ATT_SCALE) : 0.f;
            float p10 = v10 ? __expf((acc[mt][nt][2] + bd1[col])     * ATT_SCALE) : 0.f;
            float p11 = v11 ? __expf((acc[mt][nt][3] + bd1[col + 1]) * ATT_SCALE) : 0.f;
            s0 += p00 + p01;
            s1 += p10 + p11;
            *(float2*)&Sz[(size_t)r0i * KLENC + col] = make_float2(p00, p01);
            *(float2*)&Sz[(size_t)r1i * KLENC + col] = make_float2(p10, p11);
        }
        // reduce across the 4 q-lanes of this row group
        s0 += __shfl_xor_sync(0xffffffffu, s0, 1);
        s0 += __shfl_xor_sync(0xffffffffu, s0, 2);
        s1 += __shfl_xor_sync(0xffffffffu, s1, 1);
        s1 += __shfl_xor_sync(0xffffffffu, s1, 2);
        if (q == 0) {
            atomicAdd(&rz[r0i], s0);
            atomicAdd(&rz[r1i], s1);
        }
    }
}

// ============ PV: ctx = P @ V, normalized by rsum ============
#define VP 72
#define PV_STG_F (128 * SMP + 16 * VP)
#define PV_SMEM (3 * PV_STG_F * 4)

__global__ __launch_bounds__(256, 2)
void pv_mma(const float* __restrict__ S, const float* __restrict__ qkv,
            const float* __restrict__ rsum, float* __restrict__ ctx)
{
    extern __shared__ float sm_[];
    uint32_t sb = smem_u32(sm_);
    int t = threadIdx.x, wid = t >> 5, lane = t & 31, g = lane >> 2, q = lane & 3;
    int i0 = blockIdx.x * 128;
    int z = blockIdx.y, bb = z >> 4, hh = z & 15;
    int wm = (wid >> 1) * 32, wn = (wid & 1) * 32;

    const float* Arow = S + ((size_t)z * QLEN + i0 + (t >> 1)) * KLENC + (t & 1) * 8;
    uint32_t as_s = sb + (uint32_t)(((t >> 1) * SMP + (t & 1) * 8) * 4);
    int vrow = (t & 127) >> 3, vcol = (t & 7) * 8;
    uint32_t vs_s = sb + (uint32_t)((128 * SMP + vrow * VP + vcol) * 4);

    float acc[2][4][4];
    #pragma unroll
    for (int i = 0; i < 2; i++)
        #pragma unroll
        for (int j = 0; j < 4; j++)
            #pragma unroll
            for (int v = 0; v < 4; v++) acc[i][j][v] = 0.f;

    int jlim = i0 + 640; if (jlim > KLENC) jlim = KLENC;
    int NC = jlim >> 4;

    auto issue = [&](int c) {
        uint32_t off = (uint32_t)(c % 3) * PV_STG_F * 4;
        const float* ag = Arow + c * 16;
        cpa16(as_s + off, ag); cpa16(as_s + off + 16, ag + 4);
        if (t < 128) {
            const float* vg = qkv + ((size_t)((c * 16 + vrow) * 4 + bb)) * 3072 + 2048 + hh * 64 + vcol;
            cpa16(vs_s + off, vg); cpa16(vs_s + off + 16, vg + 4);
        }
        cpcommit();
    };
    issue(0);
    if (NC > 1) issue(1);

    for (int c = 0; c < NC; c++) {
        if (c + 1 < NC) asm volatile("cp.async.wait_group 1;" ::: "memory");
        else            asm volatile("cp.async.wait_group 0;" ::: "memory");
        __syncthreads();
        if (c + 2 < NC) issue(c + 2);

        const float* As = sm_ + (c % 3) * PV_STG_F;
        const float* Vs = As + 128 * SMP;
        #pragma unroll
        for (int ks = 0; ks < 16; ks += 8) {
            uint32_t af[2][4], bf[4][2];
            #pragma unroll
            for (int mt = 0; mt < 2; mt++) {
                int r = wm + mt * 16 + g;
                af[mt][0] = tf32u(As[r * SMP + ks + q]);
                af[mt][1] = tf32u(As[(r + 8) * SMP + ks + q]);
                af[mt][2] = tf32u(As[r * SMP + ks + q + 4]);
                af[mt][3] = tf32u(As[(r + 8) * SMP + ks + q + 4]);
            }
            #pragma unroll
            for (int nt = 0; nt < 4; nt++) {
                int n = wn + nt * 8 + g;
                bf[nt][0] = tf32u(Vs[(ks + q) * VP + n]);
                bf[nt][1] = tf32u(Vs[(ks + q + 4) * VP + n]);
            }
            #pragma unroll
            for (int mt = 0; mt < 2; mt++)
                #pragma unroll
                for (int nt = 0; nt < 4; nt++)
                    mma_tf32(acc[mt][nt], af[mt], bf[nt]);
        }
    }

    const float* rz = rsum + (size_t)z * QLEN;
    #pragma unroll
    for (int mt = 0; mt < 2; mt++) {
        int m = i0 + wm + mt * 16 + g;
        float inv0 = 1.f / rz[m];
        float inv1 = 1.f / rz[m + 8];
        #pragma unroll
        for (int nt = 0; nt < 4; nt++) {
            int d = wn + nt * 8 + q * 2;
            size_t o0 = ((size_t)m * 4 + bb) * 1024 + hh * 64 + d;
            size_t o1 = ((size_t)(m + 8) * 4 + bb) * 1024 + hh * 64 + d;
            *(float2*)&ctx[o0] = make_float2(acc[mt][nt][0] * inv0, acc[mt][nt][1] * inv0);
            *(float2*)&ctx[o1] = make_float2(acc[mt][nt][2] * inv1, acc[mt][nt][3] * inv1);
        }
    }
}

// ---------------- Qu/Qv prep ----------------
__global__ void quv_prep(const float* __restrict__ qkv, const float* __restrict__ u,
                         const float* __restrict__ v, float* __restrict__ Qu,
                         float* __restrict__ Qv)
{
    size_t idx = (size_t)blockIdx.x * 256 + threadIdx.x;
    int d = idx & 63;
    size_t row = idx >> 6;
    int i = row & 1023;
    int z = row >> 10, bb = z >> 4, hh = z & 15;
    float qv = qkv[((size_t)((MEMLEN + i) * 4 + bb)) * 3072 + hh * 64 + d];
    Qu[idx] = qv + u[hh * 64 + d];
    Qv[idx] = qv + v[hh * 64 + d];
}

// ---------------- weight transpose ----------------
__global__ void transpose_kernel(const float* __restrict__ in, float* __restrict__ outp,
                                 int R, int Ccols)
{
    __shared__ float tile[32][33];
    int c0 = blockIdx.x * 32, r0 = blockIdx.y * 32;
    int tx = threadIdx.x, ty = threadIdx.y;
    #pragma unroll
    for (int i = 0; i < 32; i += 8)
        tile[ty + i][tx] = in[(size_t)(r0 + ty + i) * Ccols + c0 + tx];
    __syncthreads();
    #pragma unroll
    for (int i = 0; i < 32; i += 8)
        outp[(size_t)(c0 + ty + i) * R + r0 + tx] = tile[tx][ty + i];
}

// ---------------- layernorm ----------------
__device__ __forceinline__ float block_sum256(float v, float* red)
{
    #pragma unroll
    for (int o = 16; o; o >>= 1) v += __shfl_xor_sync(0xffffffffu, v, o);
    if ((threadIdx.x & 31) == 0) red[threadIdx.x >> 5] = v;
    __syncthreads();
    float s = 0.f;
    #pragma unroll
    for (int w = 0; w < 8; w++) s += red[w];
    __syncthreads();
    return s;
}

__global__ void ln_kernel(const float* __restrict__ A, const float* __restrict__ Bv,
                          const float* __restrict__ g, const float* __restrict__ be,
                          float* __restrict__ out)
{
    int row = blockIdx.x;
    int t = threadIdx.x;
    __shared__ float red[8];
    size_t base = (size_t)row * DMODEL;

    float x[4];
    float s = 0.f;
    #pragma unroll
    for (int r = 0; r < 4; r++) {
        int c = t + r * 256;
        x[r] = A[base + c] + Bv[base + c];
        s += x[r];
    }
    float mean = block_sum256(s, red) * (1.f / DMODEL);

    float q = 0.f;
    #pragma unroll
    for (int r = 0; r < 4; r++) {
        float d = x[r] - mean;
        q += d * d;
    }
    float var = block_sum256(q, red) * (1.f / DMODEL);
    float rstd = rsqrtf(var + 1e-5f);

    #pragma unroll
    for (int r = 0; r < 4; r++) {
        int c = t + r * 256;
        out[base + c] = (x[r] - mean) * rstd * g[c] + be[c];
    }
}

// ---------------- host orchestration ----------------
extern "C" void kernel_launch(void* const* d_in, const int* in_sizes, int n_in,
                              void* d_out, int out_size)
{
    (void)in_sizes; (void)out_size;
    int off = (n_in >= 17) ? 0 : -1;
    const float* inp   = (const float*)d_in[0];
    const float* r     = (const float*)d_in[1];
    const float* u     = (const float*)d_in[2];
    const float* v     = (const float*)d_in[3];
    const float* mem   = (const float*)d_in[4];
    const float* W_qkv = (const float*)d_in[6 + off];
    const float* W_r   = (const float*)d_in[7 + off];
    const float* W_o   = (const float*)d_in[8 + off];
    const float* ln1g  = (const float*)d_in[9 + off];
    const float* ln1b  = (const float*)d_in[10 + off];
    const float* ln2g  = (const float*)d_in[11 + off];
    const float* ln2b  = (const float*)d_in[12 + off];
    const float* W1    = (const float*)d_in[13 + off];
    const float* b1    = (const float*)d_in[14 + off];
    const float* W2    = (const float*)d_in[15 + off];
    const float* b2    = (const float*)d_in[16 + off];
    float* out = (float*)d_out;

    float *cat_p, *qkv_p, *rh_p, *S_p, *BD_p, *Qu_p, *Qv_p, *rs_p, *ctx_p, *y_p, *x_p, *h_p, *y2_p;
    float *WqkvT_p, *WrT_p, *WoT_p, *W1T_p, *W2T_p;
    cudaGetSymbolAddress((void**)&cat_p, g_cat);
    cudaGetSymbolAddress((void**)&qkv_p, g_qkv);
    cudaGetSymbolAddress((void**)&rh_p,  g_rh);
    cudaGetSymbolAddress((void**)&S_p,   g_S);
    cudaGetSymbolAddress((void**)&BD_p,  g_BD);
    cudaGetSymbolAddress((void**)&Qu_p,  g_Qu);
    cudaGetSymbolAddress((void**)&Qv_p,  g_Qv);
    cudaGetSymbolAddress((void**)&rs_p,  g_rsum);
    cudaGetSymbolAddress((void**)&ctx_p, g_ctx);
    cudaGetSymbolAddress((void**)&y_p,   g_y);
    cudaGetSymbolAddress((void**)&x_p,   g_x);
    cudaGetSymbolAddress((void**)&h_p,   g_h);
    cudaGetSymbolAddress((void**)&y2_p,  g_y2);
    cudaGetSymbolAddress((void**)&WqkvT_p, g_WqkvT);
    cudaGetSymbolAddress((void**)&WrT_p,   g_WrT);
    cudaGetSymbolAddress((void**)&WoT_p,   g_WoT);
    cudaGetSymbolAddress((void**)&W1T_p,   g_W1T);
    cudaGetSymbolAddress((void**)&W2T_p,   g_W2T);

    cudaFuncSetAttribute(mm_mma,  cudaFuncAttributeMaxDynamicSharedMemorySize, MM_SMEM);
    cudaFuncSetAttribute(ac_fused, cudaFuncAttributeMaxDynamicSharedMemorySize, MM_SMEM);
    cudaFuncSetAttribute(pv_mma,  cudaFuncAttributeMaxDynamicSharedMemorySize, PV_SMEM);

    // cat = [mem; inputs]
    cudaMemcpyAsync(cat_p, mem, (size_t)MEMLEN * BATCH * DMODEL * sizeof(float),
                    cudaMemcpyDeviceToDevice);
    cudaMemcpyAsync(cat_p + (size_t)MEMLEN * BATCH * DMODEL, inp,
                    (size_t)QLEN * BATCH * DMODEL * sizeof(float),
                    cudaMemcpyDeviceToDevice);
    cudaMemsetAsync(rs_p, 0, (size_t)64 * QLEN * sizeof(float));

    // weight transposes (B^T, K-contiguous)
    dim3 tb(32, 8);
    transpose_kernel<<<dim3(3072/32, 1024/32), tb>>>(W_qkv, WqkvT_p, 1024, 3072);
    transpose_kernel<<<dim3(1024/32, 1024/32), tb>>>(W_r,   WrT_p,   1024, 1024);
    transpose_kernel<<<dim3(1024/32, 1024/32), tb>>>(W_o,   WoT_p,   1024, 1024);
    transpose_kernel<<<dim3(4096/32, 1024/32), tb>>>(W1,    W1T_p,   1024, 4096);
    transpose_kernel<<<dim3(1024/32, 4096/32), tb>>>(W2,    W2T_p,   4096, 1024);

    dim3 blk(256);
    // qkv = cat @ W_qkv
    mm_mma<<<dim3(3072/128, 6144/128, 1), blk, MM_SMEM>>>(
        cat_p, WqkvT_p, qkv_p, 6144, 3072, 1024, 1024, 1024, 3072,
        0, 0, 0, 0, 0, 0, nullptr, 0);
    // r_h = r @ W_r
    mm_mma<<<dim3(1024/128, 1536/128, 1), blk, MM_SMEM>>>(
        r, WrT_p, rh_p, 1536, 1024, 1024, 1024, 1024, 1024,
        0, 0, 0, 0, 0, 0, nullptr, 0);
    // Qu/Qv prep
    quv_prep<<<(64 * QLEN * HDIM) / 256, 256>>>(qkv_p, u, v, Qu_p, Qv_p);
    // BD[z] = Qv @ rh^T (must precede ac_fused)
    mm_mma<<<dim3(1536/128, 1024/128, 64), blk, MM_SMEM>>>(
        Qv_p, rh_p, BD_p, 1024, 1536, 64, 64, 1024, 1536,
        (long)16*1024*64, (long)1024*64, 0, 64,
        (long)16*1024*1536, (long)1024*1536, nullptr, 0);
    // P = exp(mask(AC + shift(BD)) * scale), rowsum -> rsum
    ac_fused<<<dim3(1536/128, 1024/128, 64), blk, MM_SMEM>>>(
        Qu_p, qkv_p, BD_p, S_p, rs_p);
    // ctx = (P @ V) / rsum
    pv_mma<<<dim3(QLEN/128, 64), blk, PV_SMEM>>>(S_p, qkv_p, rs_p, ctx_p);
    // y = ctx @ W_o
    mm_mma<<<dim3(1024/128, 4096/128, 1), blk, MM_SMEM>>>(
        ctx_p, WoT_p, y_p, 4096, 1024, 1024, 1024, 1024, 1024,
        0, 0, 0, 0, 0, 0, nullptr, 0);
    ln_kernel<<<NROWS, 256>>>(inp, y_p, ln1g, ln1b, x_p);
    // h = relu(x @ W1 + b1)
    mm_mma<<<dim3(4096/128, 4096/128, 1), blk, MM_SMEM>>>(
        x_p, W1T_p, h_p, 4096, 4096, 1024, 1024, 1024, 4096,
        0, 0, 0, 0, 0, 0, b1, 1);
    // y2 = h @ W2 + b2
    mm_mma<<<dim3(1024/128, 4096/128, 1), blk, MM_SMEM>>>(
        h_p, W2T_p, y2_p, 4096, 1024, 4096, 4096, 4096, 1024,
        0, 0, 0, 0, 0, 0, b2, 0);
    ln_kernel<<<NROWS, 256>>>(x_p, y2_p, ln2g, ln2b, out);
}